// round 16
// baseline (speedup 1.0000x reference)
#include <cuda_runtime.h>
#include <cuda_fp16.h>

// Problem constants
#define Bc   4
#define Vc   5
#define Jc   15
#define Hc   128
#define Wc   240
#define NPTS 128000      // 80*80*20
#define HW   (Hc * Wc)

// One pixel = 16 fp16 joints = 32 bytes = 2 uint4 halves
struct alignas(32) Pix { uint4 a, b; };

// Transposed fp16 heatmaps: (B*V, H, W) pixels of 16 halves = 19.66 MB
__device__ Pix g_hmT[(size_t)Bc * Vc * HW];

static __device__ __forceinline__ unsigned pack_h2(float lo, float hi) {
    __half2 h = __floats2half2_rn(lo, hi);
    return *reinterpret_cast<unsigned*>(&h);
}

// ---------------------------------------------------------------------------
// Kernel 1: transpose (B,V,J,H,W) f32 -> (B*V, H*W) pixels of 16 f16.
// One thread per pixel: 15 coalesced strided loads, register pack,
// 2 coalesced 128-bit stores. At its ~10us HBM floor.
// ---------------------------------------------------------------------------
__global__ void __launch_bounds__(256) transpose_kernel(const float* __restrict__ hm) {
    const int idx = blockIdx.x * blockDim.x + threadIdx.x;
    if (idx < Bc * Vc * HW) {
        const int bv  = idx / HW;
        const int pix = idx - bv * HW;

        const float* src = hm + (size_t)bv * Jc * HW + pix;
        float v[16];
#pragma unroll
        for (int j = 0; j < Jc; ++j)
            v[j] = __ldg(src + (size_t)j * HW);
        v[15] = 0.0f;

        Pix p;
        p.a.x = pack_h2(v[0],  v[1]);
        p.a.y = pack_h2(v[2],  v[3]);
        p.a.z = pack_h2(v[4],  v[5]);
        p.a.w = pack_h2(v[6],  v[7]);
        p.b.x = pack_h2(v[8],  v[9]);
        p.b.y = pack_h2(v[10], v[11]);
        p.b.z = pack_h2(v[12], v[13]);
        p.b.w = pack_h2(v[14], v[15]);
        g_hmT[idx] = p;
    }
    // PDL: signal the dependent sample_kernel once this CTA's stores are done.
    cudaTriggerProgrammaticLaunchCompletion();
}

// acc(8 joints) += w * unpack(4x half2 in a uint4)
static __device__ __forceinline__ void acc_u4(float (&acc)[8], uint4 r, float w) {
    unsigned v[4] = {r.x, r.y, r.z, r.w};
#pragma unroll
    for (int i = 0; i < 4; ++i) {
        __half2 h = *reinterpret_cast<const __half2*>(&v[i]);
        float2 u = __half22float2(h);
        acc[2 * i + 0] = fmaf(w, u.x, acc[2 * i + 0]);
        acc[2 * i + 1] = fmaf(w, u.y, acc[2 * i + 1]);
    }
}

// ---------------------------------------------------------------------------
// Kernel 2: gather, 4-lane split by (x-corner, joint-half).
// FOUR threads per (b, n): lane bit0 jl = x column (x0 or x1),
// lane bit1 jh = joint half (joints 0-7 or 8-15). Each lane loads ONE
// 16B half-pixel (LDG.128) per corner row; the quad's loads per row form a
// contiguous 64B span -> same L1 wavefront count as lane-pair, but half the
// per-thread registers and datapath, enabling 5 CTA/SM + 2-view pipeline.
// Reduction: 4-shuffle keep-quarter butterfly over the x-partner.
// ---------------------------------------------------------------------------
__global__ void __launch_bounds__(256, 5) sample_kernel(const float* __restrict__ grid,
                                                        float* __restrict__ out) {
    const int tid = blockIdx.x * blockDim.x + threadIdx.x;  // 0 .. 4*B*NPTS-1
    const int pid = tid >> 2;          // point id
    const int jl  = tid & 1;           // x-corner bit
    const int jh  = (tid >> 1) & 1;    // joint-half bit
    const int b   = pid / NPTS;
    const int n   = pid - b * NPTS;

    // PDL prologue: grid coords do NOT depend on the transpose — load them
    // before the dependency sync so these LDGs overlap the transpose kernel.
    const float2* g2 = reinterpret_cast<const float2*>(grid);
    float2 g[Vc];
#pragma unroll
    for (int v = 0; v < Vc; ++v)
        g[v] = g2[(size_t)(b * Vc + v) * NPTS + n];

    cudaGridDependencySynchronize();

    // Half-pixel granular view of the heatmaps: 2 uint4 per pixel.
    const uint4* hbase = reinterpret_cast<const uint4*>(g_hmT)
                       + (size_t)b * Vc * HW * 2 + jh;

    // Compute this lane's two half-pixel addresses + weights for view v.
    auto prep = [&](int v, const uint4*& q0, const uint4*& q1,
                    float& w0, float& w1) {
        const float ix = (g[v].x + 1.0f) * 0.5f * (float)(Wc - 1);
        const float iy = (g[v].y + 1.0f) * 0.5f * (float)(Hc - 1);
        const float x0f = floorf(ix);
        const float y0f = floorf(iy);
        const float wx1 = ix - x0f;
        const float wy1 = iy - y0f;

        int x0 = (int)x0f;
        int y0 = (int)y0f;
        x0 = max(0, min(x0, Wc - 1));
        y0 = max(0, min(y0, Hc - 1));
        const int xc = min(x0 + jl, Wc - 1);   // this lane's column
        const int y1 = min(y0 + 1, Hc - 1);

        const float wx = jl ? wx1 : (1.0f - wx1);
        w0 = wx * (1.0f - wy1);
        w1 = wx * wy1;

        const uint4* vb = hbase + (size_t)v * (HW * 2);
        q0 = vb + (unsigned)(y0 * Wc + xc) * 2u;
        q1 = vb + (unsigned)(y1 * Wc + xc) * 2u;
    };

    float acc[8];
#pragma unroll
    for (int i = 0; i < 8; ++i) acc[i] = 0.0f;

    // Double-buffered pipeline over views (raw uint4 buffers: 4 regs each).
    uint4 r0[2], r1[2];
    float w0v[2], w1v[2];
    {
        const uint4 *q0, *q1;
        prep(0, q0, q1, w0v[0], w1v[0]);
        r0[0] = __ldg(q0);
        r1[0] = __ldg(q1);
    }
#pragma unroll
    for (int v = 1; v < Vc; ++v) {
        const int cur = v & 1, prv = cur ^ 1;
        const uint4 *q0, *q1;
        prep(v, q0, q1, w0v[cur], w1v[cur]);
        r0[cur] = __ldg(q0);                 // issue view v loads ...
        r1[cur] = __ldg(q1);
        acc_u4(acc, r0[prv], w0v[prv]);      // ... while consuming view v-1
        acc_u4(acc, r1[prv], w1v[prv]);
    }
    {
        const int last = (Vc - 1) & 1;       // view 4 lives in parity 0
        acc_u4(acc, r0[last], w0v[last]);
        acc_u4(acc, r1[last], w1v[last]);
    }

    // Keep-quarter butterfly over the x-partner (xor 1, same joint-half):
    // lane jl keeps joints [jh*8 + jl*4, +4).
    float r4[4];
#pragma unroll
    for (int k = 0; k < 4; ++k) {
        const float send = jl ? acc[k] : acc[k + 4];
        const float keep = jl ? acc[k + 4] : acc[k];
        r4[k] = keep + __shfl_xor_sync(0xffffffffu, send, 1);
    }

    const int jbase = jh * 8 + jl * 4;
    const float s = 1.0f / (float)Vc;
    float* op = out + (size_t)b * Jc * NPTS + n;
#pragma unroll
    for (int k = 0; k < 4; ++k) {
        if (jbase + k < Jc) {
            float val = r4[k] * s;
            val = fminf(fmaxf(val, 0.0f), 1.0f);
            op[(size_t)(jbase + k) * NPTS] = val;
        }
    }
}

// ---------------------------------------------------------------------------
extern "C" void kernel_launch(void* const* d_in, const int* in_sizes, int n_in,
                              void* d_out, int out_size) {
    const float* heatmaps = (const float*)d_in[0];  // (4,5,15,128,240) f32
    const float* grid     = (const float*)d_in[1];  // (4,5,1,128000,2) f32
    float* out            = (float*)d_out;          // (4,15,80,80,20) f32

    (void)in_sizes; (void)n_in; (void)out_size;

    const int tp_total = Bc * Vc * HW;              // 614400
    transpose_kernel<<<(tp_total + 255) / 256, 256>>>(heatmaps);

    // Sample kernel as a programmatic dependent launch: its grid-load
    // prologue overlaps the transpose; cudaGridDependencySynchronize()
    // inside the kernel enforces ordering before g_hmT is read.
    const int total = Bc * NPTS * 4;                // 2,048,000
    cudaLaunchConfig_t cfg = {};
    cfg.gridDim  = dim3((total + 255) / 256);
    cfg.blockDim = dim3(256);
    cfg.dynamicSmemBytes = 0;
    cudaLaunchAttribute attr[1];
    attr[0].id = cudaLaunchAttributeProgrammaticStreamSerialization;
    attr[0].val.programmaticStreamSerializationAllowed = 1;
    cfg.attrs = attr;
    cfg.numAttrs = 1;
    cudaLaunchKernelEx(&cfg, sample_kernel, grid, out);
}